// round 3
// baseline (speedup 1.0000x reference)
#include <cuda_runtime.h>
#include <math.h>

// Problem dims
#define BB   4
#define NN   2048
#define DD   513
#define HH   8
#define DH   64
#define DHA  65            // 1 time + 64 space
#define ROWS (BB*NN)       // 8192

#define INV_K   10.0f
#define K_CURV  0.1f
#define EPS_F   1e-9f
#define SCALE_F 0.125f     // 1/sqrt(64)

// Scratch (device globals: allocation-free per harness rules)
__device__ float g_q[BB*HH*NN*DHA];      // time stored NEGATED -> plain 65-dot = Lorentz inner
__device__ float g_k[BB*HH*NN*DHA];
__device__ float g_v[BB*HH*NN*DHA];
__device__ float g_cat[ROWS*DD];         // [B*N][513]: col0 = t', cols 1..512 = head-concat space

// ---------------------------------------------------------------------------
// Kernel 1: QKV projection GEMM + hyperboloid time attach.
// C tile = 64 rows x 64 cols (one full head of one of q/k/v), so the per-row
// sumsq needed for the time component is fully resident in the CTA.
// ---------------------------------------------------------------------------
__global__ __launch_bounds__(256) void proj_kernel(
    const float* __restrict__ x,
    const float* __restrict__ Wq, const float* __restrict__ bq,
    const float* __restrict__ Wk, const float* __restrict__ bk,
    const float* __restrict__ Wv, const float* __restrict__ bv)
{
    __shared__ float As[16][68];   // A^T: [kk][row]
    __shared__ float Bs[16][68];   // B:   [kk][col]
    __shared__ float Cs[64][68];
    __shared__ float Ts[64];

    const int tid = threadIdx.x;
    const int ty = tid >> 4;          // 0..15 -> rows ty*4..ty*4+3
    const int tx = tid & 15;          // 0..15 -> cols tx*4..tx*4+3
    const int row0 = blockIdx.x * 64;
    const int mh = blockIdx.y;        // 0..23
    const int mat = mh >> 3;          // 0=q 1=k 2=v
    const int h = mh & 7;

    const float* W    = (mat == 0) ? Wq : ((mat == 1) ? Wk : Wv);
    const float* bias = (mat == 0) ? bq : ((mat == 1) ? bk : bv);
    float* outg       = (mat == 0) ? g_q : ((mat == 1) ? g_k : g_v);
    const float* Wh   = W + h * DD * DH;     // [513][64]
    const float* bptr = bias + h * DH;

    float acc[4][4] = {};

    for (int k0 = 0; k0 < DD; k0 += 16) {
        #pragma unroll
        for (int i = 0; i < 4; i++) {
            int lin = tid + i * 256;          // 0..1023
            int r = lin >> 4;
            int kk = lin & 15;
            int kg = k0 + kk;
            As[kk][r] = (kg < DD) ? x[(row0 + r) * DD + kg] : 0.0f;
        }
        #pragma unroll
        for (int i = 0; i < 4; i++) {
            int lin = tid + i * 256;
            int kk = lin >> 6;
            int c = lin & 63;
            int kg = k0 + kk;
            Bs[kk][c] = (kg < DD) ? Wh[kg * DH + c] : 0.0f;
        }
        __syncthreads();
        #pragma unroll
        for (int kk = 0; kk < 16; kk++) {
            float4 a4 = *(const float4*)&As[kk][ty * 4];
            float4 b4 = *(const float4*)&Bs[kk][tx * 4];
            float av[4] = {a4.x, a4.y, a4.z, a4.w};
            float bv_[4] = {b4.x, b4.y, b4.z, b4.w};
            #pragma unroll
            for (int i = 0; i < 4; i++)
                #pragma unroll
                for (int j = 0; j < 4; j++)
                    acc[i][j] += av[i] * bv_[j];
        }
        __syncthreads();
    }

    // bias + stage to smem for row reduction
    #pragma unroll
    for (int i = 0; i < 4; i++)
        #pragma unroll
        for (int j = 0; j < 4; j++)
            Cs[ty * 4 + i][tx * 4 + j] = acc[i][j] + bptr[tx * 4 + j];
    __syncthreads();

    {   // time component: t = sqrt(clip(INV_K + ||space||^2, eps)); 4 threads/row
        int r = tid >> 2;
        int part = tid & 3;
        float s = 0.0f;
        #pragma unroll
        for (int j = 0; j < 16; j++) {
            float v = Cs[r][part * 16 + j];
            s += v * v;
        }
        s += __shfl_xor_sync(0xffffffffu, s, 1);
        s += __shfl_xor_sync(0xffffffffu, s, 2);
        if (part == 0) Ts[r] = sqrtf(fmaxf(INV_K + s, EPS_F));
    }
    __syncthreads();

    const float tsign = (mat == 0) ? -1.0f : 1.0f;   // negate q's time
    for (int lin = tid; lin < 64 * DHA; lin += 256) {
        int r = lin / DHA;
        int c = lin % DHA;
        int g = row0 + r;
        int b = g >> 11;
        int n = g & 2047;
        float val = (c == 0) ? tsign * Ts[r] : Cs[r][c - 1];
        outg[((b * HH + h) * NN + n) * DHA + c] = val;
    }
}

// ---------------------------------------------------------------------------
// Kernel 2: flash attention (online softmax) + Lorentz midpoint.
// CTA: 64 query rows x full key sweep in 64-key tiles. 256 threads, 4x4 micro.
// Q/K staged transposed ([dim][row]) for float4 smem reads; P staged
// transposed ([key][row]) and V as [key][dim] for the PV phase.
// ---------------------------------------------------------------------------
#define ATT_SMEM_FLOATS (65*64 + 65*64 + 64*68 + 64*68 + 64*3)
#define ATT_SMEM_BYTES  (ATT_SMEM_FLOATS * 4)

__global__ __launch_bounds__(256) void attn_kernel()
{
    extern __shared__ float sm[];
    float* Qt   = sm;                    // [65][64]
    float* Kt   = Qt + 65 * 64;          // [65][64]
    float* Vs   = Kt + 65 * 64;          // [64][68]: space at 0..63, time at 64
    float* Pt   = Vs + 64 * 68;          // [64(key)][68(row)]; reused for O at end
    float* mrow = Pt + 64 * 68;          // [64]
    float* lrow = mrow + 64;             // [64]
    float* arow = lrow + 64;             // [64]

    const int tid = threadIdx.x;
    const int ty = tid >> 4;
    const int tx = tid & 15;
    const int bh = blockIdx.y;           // b*8 + h
    const int n0 = blockIdx.x * 64;
    const int h = bh & 7;
    const int b = bh >> 3;

    const float* qb = g_q + (size_t)(bh * NN + n0) * DHA;
    for (int lin = tid; lin < 64 * DHA; lin += 256) {
        int r = lin / DHA;
        int d = lin % DHA;
        Qt[d * 64 + r] = qb[r * DHA + d];
    }
    if (tid < 64) { mrow[tid] = -1e30f; lrow[tid] = 0.0f; }

    float o[4][4] = {};
    float ot[4] = {0.0f, 0.0f, 0.0f, 0.0f};

    const float* kbase = g_k + (size_t)bh * NN * DHA;
    const float* vbase = g_v + (size_t)bh * NN * DHA;

    for (int kt = 0; kt < NN / 64; kt++) {
        __syncthreads();   // previous iter's consumers of Kt/Vs/Pt/arow done
        const float* kb = kbase + (size_t)(kt * 64) * DHA;
        const float* vb = vbase + (size_t)(kt * 64) * DHA;
        for (int lin = tid; lin < 64 * DHA; lin += 256) {
            int r = lin / DHA;
            int d = lin % DHA;
            Kt[d * 64 + r] = kb[r * DHA + d];
            float vv = vb[r * DHA + d];
            Vs[r * 68 + ((d == 0) ? 64 : (d - 1))] = vv;
        }
        __syncthreads();

        // S = Q~ K^T (65-dim dot; time pre-negated in q)
        float s[4][4] = {};
        #pragma unroll 5
        for (int d = 0; d < DHA; d++) {
            float4 q4 = *(const float4*)&Qt[d * 64 + ty * 4];
            float4 k4 = *(const float4*)&Kt[d * 64 + tx * 4];
            float qa[4] = {q4.x, q4.y, q4.z, q4.w};
            float ka[4] = {k4.x, k4.y, k4.z, k4.w};
            #pragma unroll
            for (int i = 0; i < 4; i++)
                #pragma unroll
                for (int j = 0; j < 4; j++)
                    s[i][j] += qa[i] * ka[j];
        }
        #pragma unroll
        for (int i = 0; i < 4; i++)
            #pragma unroll
            for (int j = 0; j < 4; j++)
                Pt[(tx * 4 + j) * 68 + ty * 4 + i] = s[i][j] * SCALE_F;
        __syncthreads();

        // online softmax: 4 threads per query row (same-warp quads)
        {
            int r = tid >> 2;
            int part = tid & 3;
            float mo = mrow[r];
            float mx = -1e30f;
            #pragma unroll
            for (int j = 0; j < 16; j++)
                mx = fmaxf(mx, Pt[(part * 16 + j) * 68 + r]);
            mx = fmaxf(mx, __shfl_xor_sync(0xffffffffu, mx, 1));
            mx = fmaxf(mx, __shfl_xor_sync(0xffffffffu, mx, 2));
            float mn = fmaxf(mo, mx);
            float sum = 0.0f;
            #pragma unroll
            for (int j = 0; j < 16; j++) {
                int kk = part * 16 + j;
                float v = __expf(Pt[kk * 68 + r] - mn);
                Pt[kk * 68 + r] = v;
                sum += v;
            }
            sum += __shfl_xor_sync(0xffffffffu, sum, 1);
            sum += __shfl_xor_sync(0xffffffffu, sum, 2);
            if (part == 0) {
                float al = __expf(mo - mn);
                arow[r] = al;
                lrow[r] = lrow[r] * al + sum;
                mrow[r] = mn;
            }
        }
        __syncthreads();

        // O = O*alpha + P @ V   (65 output dims: 64 space via tx grid, time on tx==0)
        float acc[4][4] = {};
        float tacc[4] = {0.0f, 0.0f, 0.0f, 0.0f};
        #pragma unroll 4
        for (int kk = 0; kk < 64; kk++) {
            float4 p4 = *(const float4*)&Pt[kk * 68 + ty * 4];
            float4 v4 = *(const float4*)&Vs[kk * 68 + tx * 4];
            float pa[4] = {p4.x, p4.y, p4.z, p4.w};
            float va[4] = {v4.x, v4.y, v4.z, v4.w};
            #pragma unroll
            for (int i = 0; i < 4; i++)
                #pragma unroll
                for (int j = 0; j < 4; j++)
                    acc[i][j] += pa[i] * va[j];
            if (tx == 0) {
                float vt = Vs[kk * 68 + 64];
                #pragma unroll
                for (int i = 0; i < 4; i++) tacc[i] += pa[i] * vt;
            }
        }
        #pragma unroll
        for (int i = 0; i < 4; i++) {
            float al = arow[ty * 4 + i];
            #pragma unroll
            for (int j = 0; j < 4; j++) o[i][j] = o[i][j] * al + acc[i][j];
            ot[i] = ot[i] * al + tacc[i];
        }
    }
    __syncthreads();

    // finalize: s = O/l staged into Pt as [row][dim] (time at col 64)
    #pragma unroll
    for (int i = 0; i < 4; i++) {
        float invl = 1.0f / lrow[ty * 4 + i];
        #pragma unroll
        for (int j = 0; j < 4; j++)
            Pt[(ty * 4 + i) * 68 + tx * 4 + j] = o[i][j] * invl;
        if (tx == 0) Pt[(ty * 4 + i) * 68 + 64] = ot[i] * invl;
    }
    __syncthreads();

    {   // midpoint factor = 1/sqrt(clip(-k*(-t^2 + ||s||^2), eps))
        int r = tid >> 2;
        int part = tid & 3;
        float ss = 0.0f;
        #pragma unroll
        for (int j = 0; j < 16; j++) {
            float v = Pt[r * 68 + part * 16 + j];
            ss += v * v;
        }
        ss += __shfl_xor_sync(0xffffffffu, ss, 1);
        ss += __shfl_xor_sync(0xffffffffu, ss, 2);
        if (part == 0) {
            float t = Pt[r * 68 + 64];
            float inner = ss - t * t;
            arow[r] = rsqrtf(fmaxf(-K_CURV * inner, EPS_F));
        }
    }
    __syncthreads();

    // write normalized space parts into head-concat layout
    for (int lin = tid; lin < 64 * 64; lin += 256) {
        int r = lin >> 6;
        int c = lin & 63;
        int grow = b * NN + n0 + r;
        g_cat[(size_t)grow * DD + 1 + h * DH + c] = Pt[r * 68 + c] * arow[r];
    }
}

// ---------------------------------------------------------------------------
// Kernel 3/5: per-row time attach: col0 = sqrt(clip(INV_K + sumsq(cols 1..512)))
// One warp per row. which=1 -> g_cat, which=0 -> outp.
// ---------------------------------------------------------------------------
__global__ void rowtime_kernel(float* outp, int which)
{
    float* buf = which ? g_cat : outp;
    int warp = (blockIdx.x * blockDim.x + threadIdx.x) >> 5;
    int lane = threadIdx.x & 31;
    if (warp >= ROWS) return;
    const float* row = buf + (size_t)warp * DD + 1;
    float s = 0.0f;
    #pragma unroll
    for (int c = lane; c < 512; c += 32) {
        float v = row[c];
        s += v * v;
    }
    #pragma unroll
    for (int off = 16; off; off >>= 1)
        s += __shfl_xor_sync(0xffffffffu, s, off);
    if (lane == 0) buf[(size_t)warp * DD] = sqrtf(fmaxf(INV_K + s, EPS_F));
}

// ---------------------------------------------------------------------------
// Kernel 4: output GEMM: d_out[:,1:513] = g_cat[8192,513] @ Wo[513,512] + bo
// ---------------------------------------------------------------------------
__global__ __launch_bounds__(256) void outproj_kernel(
    const float* __restrict__ Wo, const float* __restrict__ bo,
    float* __restrict__ outp)
{
    __shared__ float As[16][68];
    __shared__ float Bs[16][68];

    const int tid = threadIdx.x;
    const int ty = tid >> 4;
    const int tx = tid & 15;
    const int row0 = blockIdx.x * 64;
    const int col0 = blockIdx.y * 64;

    float acc[4][4] = {};

    for (int k0 = 0; k0 < DD; k0 += 16) {
        #pragma unroll
        for (int i = 0; i < 4; i++) {
            int lin = tid + i * 256;
            int r = lin >> 4;
            int kk = lin & 15;
            int kg = k0 + kk;
            As[kk][r] = (kg < DD) ? g_cat[(size_t)(row0 + r) * DD + kg] : 0.0f;
        }
        #pragma unroll
        for (int i = 0; i < 4; i++) {
            int lin = tid + i * 256;
            int kk = lin >> 6;
            int c = lin & 63;
            int kg = k0 + kk;
            Bs[kk][c] = (kg < DD) ? Wo[(size_t)kg * 512 + col0 + c] : 0.0f;
        }
        __syncthreads();
        #pragma unroll
        for (int kk = 0; kk < 16; kk++) {
            float4 a4 = *(const float4*)&As[kk][ty * 4];
            float4 b4 = *(const float4*)&Bs[kk][tx * 4];
            float av[4] = {a4.x, a4.y, a4.z, a4.w};
            float bv_[4] = {b4.x, b4.y, b4.z, b4.w};
            #pragma unroll
            for (int i = 0; i < 4; i++)
                #pragma unroll
                for (int j = 0; j < 4; j++)
                    acc[i][j] += av[i] * bv_[j];
        }
        __syncthreads();
    }

    #pragma unroll
    for (int i = 0; i < 4; i++) {
        int r = row0 + ty * 4 + i;
        #pragma unroll
        for (int j = 0; j < 4; j++) {
            int c = col0 + tx * 4 + j;
            outp[(size_t)r * DD + 1 + c] = acc[i][j] + bo[c];
        }
    }
}

// ---------------------------------------------------------------------------
extern "C" void kernel_launch(void* const* d_in, const int* in_sizes, int n_in,
                              void* d_out, int out_size)
{
    const float* x  = (const float*)d_in[0];
    const float* Wq = (const float*)d_in[1];
    const float* bq = (const float*)d_in[2];
    const float* Wk = (const float*)d_in[3];
    const float* bk = (const float*)d_in[4];
    const float* Wv = (const float*)d_in[5];
    const float* bv = (const float*)d_in[6];
    const float* Wo = (const float*)d_in[7];
    const float* bo = (const float*)d_in[8];
    float* outp = (float*)d_out;

    cudaFuncSetAttribute(attn_kernel,
                         cudaFuncAttributeMaxDynamicSharedMemorySize,
                         ATT_SMEM_BYTES);

    // 1. QKV projections (+time attach, q-time negated)
    proj_kernel<<<dim3(ROWS / 64, 24), 256>>>(x, Wq, bq, Wk, bk, Wv, bv);
    // 2. flash attention + Lorentz midpoint -> g_cat space columns
    attn_kernel<<<dim3(NN / 64, BB * HH), 256, ATT_SMEM_BYTES>>>();
    // 3. concat time component t'
    rowtime_kernel<<<ROWS / 8, 256>>>(nullptr, 1);
    // 4. output projection into d_out[:,1:]
    outproj_kernel<<<dim3(ROWS / 64, 8), 256>>>(Wo, bo, outp);
    // 5. final time attach into d_out[:,0]
    rowtime_kernel<<<ROWS / 8, 256>>>(outp, 0);
}

// round 4
// speedup vs baseline: 1.0002x; 1.0002x over previous
#include <cuda_runtime.h>
#include <math.h>

// Problem dims
#define BB   4
#define NN   2048
#define DD   513
#define HH   8
#define DH   64
#define DHA  65            // 1 time + 64 space
#define ROWS (BB*NN)       // 8192

#define INV_K   10.0f
#define K_CURV  0.1f
#define EPS_F   1e-9f
#define SCALE_F 0.125f     // 1/sqrt(64)

// Scratch (device globals: allocation-free per harness rules)
__device__ float g_q[BB*HH*NN*DHA];      // time stored NEGATED -> plain 65-dot = Lorentz inner
__device__ float g_k[BB*HH*NN*DHA];
__device__ float g_v[BB*HH*NN*DHA];
__device__ float g_cat[ROWS*DD];         // [B*N][513]: col0 = t', cols 1..512 = head-concat space

// ---------------------------------------------------------------------------
// Kernel 1: QKV projection GEMM + hyperboloid time attach.
// C tile = 64 rows x 64 cols (one full head of one of q/k/v), so the per-row
// sumsq needed for the time component is fully resident in the CTA.
// ---------------------------------------------------------------------------
__global__ __launch_bounds__(256) void proj_kernel(
    const float* __restrict__ x,
    const float* __restrict__ Wq, const float* __restrict__ bq,
    const float* __restrict__ Wk, const float* __restrict__ bk,
    const float* __restrict__ Wv, const float* __restrict__ bv)
{
    __shared__ float As[16][68];   // A^T: [kk][row]
    __shared__ float Bs[16][68];   // B:   [kk][col]
    __shared__ float Cs[64][68];
    __shared__ float Ts[64];

    const int tid = threadIdx.x;
    const int ty = tid >> 4;          // 0..15 -> rows ty*4..ty*4+3
    const int tx = tid & 15;          // 0..15 -> cols tx*4..tx*4+3
    const int row0 = blockIdx.x * 64;
    const int mh = blockIdx.y;        // 0..23
    const int mat = mh >> 3;          // 0=q 1=k 2=v
    const int h = mh & 7;

    const float* W    = (mat == 0) ? Wq : ((mat == 1) ? Wk : Wv);
    const float* bias = (mat == 0) ? bq : ((mat == 1) ? bk : bv);
    float* outg       = (mat == 0) ? g_q : ((mat == 1) ? g_k : g_v);
    const float* Wh   = W + h * DD * DH;     // [513][64]
    const float* bptr = bias + h * DH;

    float acc[4][4] = {};

    for (int k0 = 0; k0 < DD; k0 += 16) {
        #pragma unroll
        for (int i = 0; i < 4; i++) {
            int lin = tid + i * 256;          // 0..1023
            int r = lin >> 4;
            int kk = lin & 15;
            int kg = k0 + kk;
            As[kk][r] = (kg < DD) ? x[(row0 + r) * DD + kg] : 0.0f;
        }
        #pragma unroll
        for (int i = 0; i < 4; i++) {
            int lin = tid + i * 256;
            int kk = lin >> 6;
            int c = lin & 63;
            int kg = k0 + kk;
            Bs[kk][c] = (kg < DD) ? Wh[kg * DH + c] : 0.0f;
        }
        __syncthreads();
        #pragma unroll
        for (int kk = 0; kk < 16; kk++) {
            float4 a4 = *(const float4*)&As[kk][ty * 4];
            float4 b4 = *(const float4*)&Bs[kk][tx * 4];
            float av[4] = {a4.x, a4.y, a4.z, a4.w};
            float bv_[4] = {b4.x, b4.y, b4.z, b4.w};
            #pragma unroll
            for (int i = 0; i < 4; i++)
                #pragma unroll
                for (int j = 0; j < 4; j++)
                    acc[i][j] += av[i] * bv_[j];
        }
        __syncthreads();
    }

    // bias + stage to smem for row reduction
    #pragma unroll
    for (int i = 0; i < 4; i++)
        #pragma unroll
        for (int j = 0; j < 4; j++)
            Cs[ty * 4 + i][tx * 4 + j] = acc[i][j] + bptr[tx * 4 + j];
    __syncthreads();

    {   // time component: t = sqrt(clip(INV_K + ||space||^2, eps)); 4 threads/row
        int r = tid >> 2;
        int part = tid & 3;
        float s = 0.0f;
        #pragma unroll
        for (int j = 0; j < 16; j++) {
            float v = Cs[r][part * 16 + j];
            s += v * v;
        }
        s += __shfl_xor_sync(0xffffffffu, s, 1);
        s += __shfl_xor_sync(0xffffffffu, s, 2);
        if (part == 0) Ts[r] = sqrtf(fmaxf(INV_K + s, EPS_F));
    }
    __syncthreads();

    const float tsign = (mat == 0) ? -1.0f : 1.0f;   // negate q's time
    for (int lin = tid; lin < 64 * DHA; lin += 256) {
        int r = lin / DHA;
        int c = lin % DHA;
        int g = row0 + r;
        int b = g >> 11;
        int n = g & 2047;
        float val = (c == 0) ? tsign * Ts[r] : Cs[r][c - 1];
        outg[((b * HH + h) * NN + n) * DHA + c] = val;
    }
}

// ---------------------------------------------------------------------------
// Kernel 2: flash attention (online softmax) + Lorentz midpoint.
// CTA: 64 query rows x full key sweep in 64-key tiles. 256 threads, 4x4 micro.
// Q/K staged transposed ([dim][row]) for float4 smem reads; P staged
// transposed ([key][row]) and V as [key][dim] for the PV phase.
// ---------------------------------------------------------------------------
#define ATT_SMEM_FLOATS (65*64 + 65*64 + 64*68 + 64*68 + 64*3)
#define ATT_SMEM_BYTES  (ATT_SMEM_FLOATS * 4)

__global__ __launch_bounds__(256) void attn_kernel()
{
    extern __shared__ float sm[];
    float* Qt   = sm;                    // [65][64]
    float* Kt   = Qt + 65 * 64;          // [65][64]
    float* Vs   = Kt + 65 * 64;          // [64][68]: space at 0..63, time at 64
    float* Pt   = Vs + 64 * 68;          // [64(key)][68(row)]; reused for O at end
    float* mrow = Pt + 64 * 68;          // [64]
    float* lrow = mrow + 64;             // [64]
    float* arow = lrow + 64;             // [64]

    const int tid = threadIdx.x;
    const int ty = tid >> 4;
    const int tx = tid & 15;
    const int bh = blockIdx.y;           // b*8 + h
    const int n0 = blockIdx.x * 64;
    const int h = bh & 7;
    const int b = bh >> 3;

    const float* qb = g_q + (size_t)(bh * NN + n0) * DHA;
    for (int lin = tid; lin < 64 * DHA; lin += 256) {
        int r = lin / DHA;
        int d = lin % DHA;
        Qt[d * 64 + r] = qb[r * DHA + d];
    }
    if (tid < 64) { mrow[tid] = -1e30f; lrow[tid] = 0.0f; }

    float o[4][4] = {};
    float ot[4] = {0.0f, 0.0f, 0.0f, 0.0f};

    const float* kbase = g_k + (size_t)bh * NN * DHA;
    const float* vbase = g_v + (size_t)bh * NN * DHA;

    for (int kt = 0; kt < NN / 64; kt++) {
        __syncthreads();   // previous iter's consumers of Kt/Vs/Pt/arow done
        const float* kb = kbase + (size_t)(kt * 64) * DHA;
        const float* vb = vbase + (size_t)(kt * 64) * DHA;
        for (int lin = tid; lin < 64 * DHA; lin += 256) {
            int r = lin / DHA;
            int d = lin % DHA;
            Kt[d * 64 + r] = kb[r * DHA + d];
            float vv = vb[r * DHA + d];
            Vs[r * 68 + ((d == 0) ? 64 : (d - 1))] = vv;
        }
        __syncthreads();

        // S = Q~ K^T (65-dim dot; time pre-negated in q)
        float s[4][4] = {};
        #pragma unroll 5
        for (int d = 0; d < DHA; d++) {
            float4 q4 = *(const float4*)&Qt[d * 64 + ty * 4];
            float4 k4 = *(const float4*)&Kt[d * 64 + tx * 4];
            float qa[4] = {q4.x, q4.y, q4.z, q4.w};
            float ka[4] = {k4.x, k4.y, k4.z, k4.w};
            #pragma unroll
            for (int i = 0; i < 4; i++)
                #pragma unroll
                for (int j = 0; j < 4; j++)
                    s[i][j] += qa[i] * ka[j];
        }
        #pragma unroll
        for (int i = 0; i < 4; i++)
            #pragma unroll
            for (int j = 0; j < 4; j++)
                Pt[(tx * 4 + j) * 68 + ty * 4 + i] = s[i][j] * SCALE_F;
        __syncthreads();

        // online softmax: 4 threads per query row (same-warp quads)
        {
            int r = tid >> 2;
            int part = tid & 3;
            float mo = mrow[r];
            float mx = -1e30f;
            #pragma unroll
            for (int j = 0; j < 16; j++)
                mx = fmaxf(mx, Pt[(part * 16 + j) * 68 + r]);
            mx = fmaxf(mx, __shfl_xor_sync(0xffffffffu, mx, 1));
            mx = fmaxf(mx, __shfl_xor_sync(0xffffffffu, mx, 2));
            float mn = fmaxf(mo, mx);
            float sum = 0.0f;
            #pragma unroll
            for (int j = 0; j < 16; j++) {
                int kk = part * 16 + j;
                float v = __expf(Pt[kk * 68 + r] - mn);
                Pt[kk * 68 + r] = v;
                sum += v;
            }
            sum += __shfl_xor_sync(0xffffffffu, sum, 1);
            sum += __shfl_xor_sync(0xffffffffu, sum, 2);
            if (part == 0) {
                float al = __expf(mo - mn);
                arow[r] = al;
                lrow[r] = lrow[r] * al + sum;
                mrow[r] = mn;
            }
        }
        __syncthreads();

        // O = O*alpha + P @ V   (65 output dims: 64 space via tx grid, time on tx==0)
        float acc[4][4] = {};
        float tacc[4] = {0.0f, 0.0f, 0.0f, 0.0f};
        #pragma unroll 4
        for (int kk = 0; kk < 64; kk++) {
            float4 p4 = *(const float4*)&Pt[kk * 68 + ty * 4];
            float4 v4 = *(const float4*)&Vs[kk * 68 + tx * 4];
            float pa[4] = {p4.x, p4.y, p4.z, p4.w};
            float va[4] = {v4.x, v4.y, v4.z, v4.w};
            #pragma unroll
            for (int i = 0; i < 4; i++)
                #pragma unroll
                for (int j = 0; j < 4; j++)
                    acc[i][j] += pa[i] * va[j];
            if (tx == 0) {
                float vt = Vs[kk * 68 + 64];
                #pragma unroll
                for (int i = 0; i < 4; i++) tacc[i] += pa[i] * vt;
            }
        }
        #pragma unroll
        for (int i = 0; i < 4; i++) {
            float al = arow[ty * 4 + i];
            #pragma unroll
            for (int j = 0; j < 4; j++) o[i][j] = o[i][j] * al + acc[i][j];
            ot[i] = ot[i] * al + tacc[i];
        }
    }
    __syncthreads();

    // finalize: s = O/l staged into Pt as [row][dim] (time at col 64)
    #pragma unroll
    for (int i = 0; i < 4; i++) {
        float invl = 1.0f / lrow[ty * 4 + i];
        #pragma unroll
        for (int j = 0; j < 4; j++)
            Pt[(ty * 4 + i) * 68 + tx * 4 + j] = o[i][j] * invl;
        if (tx == 0) Pt[(ty * 4 + i) * 68 + 64] = ot[i] * invl;
    }
    __syncthreads();

    {   // midpoint factor = 1/sqrt(clip(-k*(-t^2 + ||s||^2), eps))
        int r = tid >> 2;
        int part = tid & 3;
        float ss = 0.0f;
        #pragma unroll
        for (int j = 0; j < 16; j++) {
            float v = Pt[r * 68 + part * 16 + j];
            ss += v * v;
        }
        ss += __shfl_xor_sync(0xffffffffu, ss, 1);
        ss += __shfl_xor_sync(0xffffffffu, ss, 2);
        if (part == 0) {
            float t = Pt[r * 68 + 64];
            float inner = ss - t * t;
            arow[r] = rsqrtf(fmaxf(-K_CURV * inner, EPS_F));
        }
    }
    __syncthreads();

    // write normalized space parts into head-concat layout
    for (int lin = tid; lin < 64 * 64; lin += 256) {
        int r = lin >> 6;
        int c = lin & 63;
        int grow = b * NN + n0 + r;
        g_cat[(size_t)grow * DD + 1 + h * DH + c] = Pt[r * 68 + c] * arow[r];
    }
}

// ---------------------------------------------------------------------------
// Kernel 3/5: per-row time attach: col0 = sqrt(clip(INV_K + sumsq(cols 1..512)))
// One warp per row. which=1 -> g_cat, which=0 -> outp.
// ---------------------------------------------------------------------------
__global__ void rowtime_kernel(float* outp, int which)
{
    float* buf = which ? g_cat : outp;
    int warp = (blockIdx.x * blockDim.x + threadIdx.x) >> 5;
    int lane = threadIdx.x & 31;
    if (warp >= ROWS) return;
    const float* row = buf + (size_t)warp * DD + 1;
    float s = 0.0f;
    #pragma unroll
    for (int c = lane; c < 512; c += 32) {
        float v = row[c];
        s += v * v;
    }
    #pragma unroll
    for (int off = 16; off; off >>= 1)
        s += __shfl_xor_sync(0xffffffffu, s, off);
    if (lane == 0) buf[(size_t)warp * DD] = sqrtf(fmaxf(INV_K + s, EPS_F));
}

// ---------------------------------------------------------------------------
// Kernel 4: output GEMM: d_out[:,1:513] = g_cat[8192,513] @ Wo[513,512] + bo
// ---------------------------------------------------------------------------
__global__ __launch_bounds__(256) void outproj_kernel(
    const float* __restrict__ Wo, const float* __restrict__ bo,
    float* __restrict__ outp)
{
    __shared__ float As[16][68];
    __shared__ float Bs[16][68];

    const int tid = threadIdx.x;
    const int ty = tid >> 4;
    const int tx = tid & 15;
    const int row0 = blockIdx.x * 64;
    const int col0 = blockIdx.y * 64;

    float acc[4][4] = {};

    for (int k0 = 0; k0 < DD; k0 += 16) {
        #pragma unroll
        for (int i = 0; i < 4; i++) {
            int lin = tid + i * 256;
            int r = lin >> 4;
            int kk = lin & 15;
            int kg = k0 + kk;
            As[kk][r] = (kg < DD) ? g_cat[(size_t)(row0 + r) * DD + kg] : 0.0f;
        }
        #pragma unroll
        for (int i = 0; i < 4; i++) {
            int lin = tid + i * 256;
            int kk = lin >> 6;
            int c = lin & 63;
            int kg = k0 + kk;
            Bs[kk][c] = (kg < DD) ? Wo[(size_t)kg * 512 + col0 + c] : 0.0f;
        }
        __syncthreads();
        #pragma unroll
        for (int kk = 0; kk < 16; kk++) {
            float4 a4 = *(const float4*)&As[kk][ty * 4];
            float4 b4 = *(const float4*)&Bs[kk][tx * 4];
            float av[4] = {a4.x, a4.y, a4.z, a4.w};
            float bv_[4] = {b4.x, b4.y, b4.z, b4.w};
            #pragma unroll
            for (int i = 0; i < 4; i++)
                #pragma unroll
                for (int j = 0; j < 4; j++)
                    acc[i][j] += av[i] * bv_[j];
        }
        __syncthreads();
    }

    #pragma unroll
    for (int i = 0; i < 4; i++) {
        int r = row0 + ty * 4 + i;
        #pragma unroll
        for (int j = 0; j < 4; j++) {
            int c = col0 + tx * 4 + j;
            outp[(size_t)r * DD + 1 + c] = acc[i][j] + bo[c];
        }
    }
}

// ---------------------------------------------------------------------------
extern "C" void kernel_launch(void* const* d_in, const int* in_sizes, int n_in,
                              void* d_out, int out_size)
{
    const float* x  = (const float*)d_in[0];
    const float* Wq = (const float*)d_in[1];
    const float* bq = (const float*)d_in[2];
    const float* Wk = (const float*)d_in[3];
    const float* bk = (const float*)d_in[4];
    const float* Wv = (const float*)d_in[5];
    const float* bv = (const float*)d_in[6];
    const float* Wo = (const float*)d_in[7];
    const float* bo = (const float*)d_in[8];
    float* outp = (float*)d_out;

    cudaFuncSetAttribute(attn_kernel,
                         cudaFuncAttributeMaxDynamicSharedMemorySize,
                         ATT_SMEM_BYTES);

    // 1. QKV projections (+time attach, q-time negated)
    proj_kernel<<<dim3(ROWS / 64, 24), 256>>>(x, Wq, bq, Wk, bk, Wv, bv);
    // 2. flash attention + Lorentz midpoint -> g_cat space columns
    attn_kernel<<<dim3(NN / 64, BB * HH), 256, ATT_SMEM_BYTES>>>();
    // 3. concat time component t'
    rowtime_kernel<<<ROWS / 8, 256>>>(nullptr, 1);
    // 4. output projection into d_out[:,1:]
    outproj_kernel<<<dim3(ROWS / 64, 8), 256>>>(Wo, bo, outp);
    // 5. final time attach into d_out[:,0]
    rowtime_kernel<<<ROWS / 8, 256>>>(outp, 0);
}

// round 5
// speedup vs baseline: 1.0637x; 1.0635x over previous
#include <cuda_runtime.h>
#include <math.h>

// Problem dims
#define BB   4
#define NN   2048
#define DD   513
#define HH   8
#define DH   64
#define DHA  65            // 1 time + 64 space
#define ROWS (BB*NN)       // 8192

#define INV_K   10.0f
#define K_CURV  0.1f
#define EPS_F   1e-9f
#define SCALE_F 0.125f     // 1/sqrt(64)

// ---------------------------------------------------------------------------
// Packed fp32x2 helpers (sm_100+ PTX fma.rn.f32x2 -> FFMA2; doubles FMA rate)
// ---------------------------------------------------------------------------
typedef unsigned long long u64;
__device__ __forceinline__ u64 pk2(float x, float y) {
    u64 r; asm("mov.b64 %0, {%1,%2};" : "=l"(r) : "f"(x), "f"(y)); return r;
}
__device__ __forceinline__ u64 bc2(float x) {
    u64 r; asm("mov.b64 %0, {%1,%1};" : "=l"(r) : "f"(x)); return r;
}
__device__ __forceinline__ void fma2(u64 &d, u64 a, u64 b) {
    asm("fma.rn.f32x2 %0, %1, %2, %0;" : "+l"(d) : "l"(a), "l"(b));
}
__device__ __forceinline__ u64 fma2v(u64 a, u64 b, u64 c) {
    u64 d; asm("fma.rn.f32x2 %0, %1, %2, %3;" : "=l"(d) : "l"(a), "l"(b), "l"(c)); return d;
}
__device__ __forceinline__ u64 mul2(u64 a, u64 b) {
    u64 d; asm("mul.rn.f32x2 %0, %1, %2;" : "=l"(d) : "l"(a), "l"(b)); return d;
}
__device__ __forceinline__ float2 up2(u64 v) {
    float lo, hi; asm("mov.b64 {%0,%1}, %2;" : "=f"(lo), "=f"(hi) : "l"(v));
    return make_float2(lo, hi);
}

// Scratch (device globals: allocation-free per harness rules)
__device__ float g_q[BB*HH*NN*DHA];      // time stored NEGATED -> plain 65-dot = Lorentz inner
__device__ float g_k[BB*HH*NN*DHA];
__device__ float g_v[BB*HH*NN*DHA];
__device__ float g_cat[ROWS*DD];         // [B*N][513]: col0 = t', cols 1..512 = head-concat space

// ---------------------------------------------------------------------------
// Kernel 1: QKV projection GEMM + hyperboloid time attach.
// 64x64 C tile, 256 threads, 4x4 micro-tile via packed f32x2 FMAs.
// Accumulator pairs run along columns (free pairs from B's float4 loads).
// ---------------------------------------------------------------------------
__global__ __launch_bounds__(256) void proj_kernel(
    const float* __restrict__ x,
    const float* __restrict__ Wq, const float* __restrict__ bq,
    const float* __restrict__ Wk, const float* __restrict__ bk,
    const float* __restrict__ Wv, const float* __restrict__ bv)
{
    __shared__ float As[16][68];   // A^T: [kk][row]
    __shared__ float Bs[16][68];   // B:   [kk][col]
    __shared__ float Cs[64][68];
    __shared__ float Ts[64];

    const int tid = threadIdx.x;
    const int ty = tid >> 4;          // rows ty*4..+3
    const int tx = tid & 15;          // cols tx*4..+3
    const int row0 = blockIdx.x * 64;
    const int mh = blockIdx.y;        // 0..23
    const int mat = mh >> 3;          // 0=q 1=k 2=v
    const int h = mh & 7;

    const float* W    = (mat == 0) ? Wq : ((mat == 1) ? Wk : Wv);
    const float* bias = (mat == 0) ? bq : ((mat == 1) ? bk : bv);
    float* outg       = (mat == 0) ? g_q : ((mat == 1) ? g_k : g_v);
    const float* Wh   = W + h * DD * DH;     // [513][64]
    const float* bptr = bias + h * DH;

    u64 acc2[4][2] = {};              // [row i][col-pair p]

    for (int k0 = 0; k0 < DD; k0 += 16) {
        #pragma unroll
        for (int i = 0; i < 4; i++) {
            int lin = tid + i * 256;
            int r = lin >> 4;
            int kk = lin & 15;
            int kg = k0 + kk;
            As[kk][r] = (kg < DD) ? x[(row0 + r) * DD + kg] : 0.0f;
        }
        #pragma unroll
        for (int i = 0; i < 4; i++) {
            int lin = tid + i * 256;
            int kk = lin >> 6;
            int c = lin & 63;
            int kg = k0 + kk;
            Bs[kk][c] = (kg < DD) ? Wh[kg * DH + c] : 0.0f;
        }
        __syncthreads();
        #pragma unroll
        for (int kk = 0; kk < 16; kk++) {
            float4 a4 = *(const float4*)&As[kk][ty * 4];
            float4 b4 = *(const float4*)&Bs[kk][tx * 4];
            u64 bp0 = pk2(b4.x, b4.y);
            u64 bp1 = pk2(b4.z, b4.w);
            float av[4] = {a4.x, a4.y, a4.z, a4.w};
            #pragma unroll
            for (int i = 0; i < 4; i++) {
                u64 ab = bc2(av[i]);
                fma2(acc2[i][0], ab, bp0);
                fma2(acc2[i][1], ab, bp1);
            }
        }
        __syncthreads();
    }

    // bias + stage to smem for row reduction (float4 stores)
    {
        float4 bb = *(const float4*)&bptr[tx * 4];
        #pragma unroll
        for (int i = 0; i < 4; i++) {
            float2 c01 = up2(acc2[i][0]);
            float2 c23 = up2(acc2[i][1]);
            float4 cv = make_float4(c01.x + bb.x, c01.y + bb.y,
                                    c23.x + bb.z, c23.y + bb.w);
            *(float4*)&Cs[ty * 4 + i][tx * 4] = cv;
        }
    }
    __syncthreads();

    {   // time component: t = sqrt(clip(INV_K + ||space||^2, eps)); 4 threads/row
        int r = tid >> 2;
        int part = tid & 3;
        float s = 0.0f;
        #pragma unroll
        for (int j = 0; j < 16; j++) {
            float v = Cs[r][part * 16 + j];
            s += v * v;
        }
        s += __shfl_xor_sync(0xffffffffu, s, 1);
        s += __shfl_xor_sync(0xffffffffu, s, 2);
        if (part == 0) Ts[r] = sqrtf(fmaxf(INV_K + s, EPS_F));
    }
    __syncthreads();

    const float tsign = (mat == 0) ? -1.0f : 1.0f;   // negate q's time
    for (int lin = tid; lin < 64 * DHA; lin += 256) {
        int r = lin / DHA;
        int c = lin % DHA;
        int g = row0 + r;
        int b = g >> 11;
        int n = g & 2047;
        float val = (c == 0) ? tsign * Ts[r] : Cs[r][c - 1];
        outg[((b * HH + h) * NN + n) * DHA + c] = val;
    }
}

// ---------------------------------------------------------------------------
// Kernel 2: flash attention (online softmax) + Lorentz midpoint, f32x2 math.
// CTA: 64 query rows x full key sweep in 64-key tiles. 256 threads, 4x4 micro.
// Time-column PV accumulation folded into the softmax exp loop (otacc).
// ---------------------------------------------------------------------------
#define ATT_SMEM_FLOATS (65*64 + 65*64 + 64*68 + 64*68 + 64*4)
#define ATT_SMEM_BYTES  (ATT_SMEM_FLOATS * 4)

__global__ __launch_bounds__(256) void attn_kernel()
{
    extern __shared__ float sm[];
    float* Qt    = sm;                    // [65][64]
    float* Kt    = Qt + 65 * 64;          // [65][64]
    float* Vs    = Kt + 65 * 64;          // [64][68]: space 0..63, time at 64
    float* Pt    = Vs + 64 * 68;          // [64(key)][68(row)]; reused for O at end
    float* mrow  = Pt + 64 * 68;          // [64]
    float* lrow  = mrow + 64;             // [64]
    float* arow  = lrow + 64;             // [64]
    float* otacc = arow + 64;             // [64] time-component accumulator

    const int tid = threadIdx.x;
    const int ty = tid >> 4;
    const int tx = tid & 15;
    const int bh = blockIdx.y;           // b*8 + h
    const int n0 = blockIdx.x * 64;
    const int h = bh & 7;
    const int b = bh >> 3;

    const float* qb = g_q + (size_t)(bh * NN + n0) * DHA;
    for (int lin = tid; lin < 64 * DHA; lin += 256) {
        int r = lin / DHA;
        int d = lin % DHA;
        Qt[d * 64 + r] = qb[r * DHA + d];
    }
    if (tid < 64) { mrow[tid] = -1e30f; lrow[tid] = 0.0f; otacc[tid] = 0.0f; }

    u64 o2[4][2] = {};                   // [row i][col-pair p], persistent

    const float* kbase = g_k + (size_t)bh * NN * DHA;
    const float* vbase = g_v + (size_t)bh * NN * DHA;

    for (int kt = 0; kt < NN / 64; kt++) {
        __syncthreads();   // previous iter's consumers of Kt/Vs/Pt/arow done
        const float* kb = kbase + (size_t)(kt * 64) * DHA;
        const float* vb = vbase + (size_t)(kt * 64) * DHA;
        for (int lin = tid; lin < 64 * DHA; lin += 256) {
            int r = lin / DHA;
            int d = lin % DHA;
            Kt[d * 64 + r] = kb[r * DHA + d];
            float vv = vb[r * DHA + d];
            Vs[r * 68 + ((d == 0) ? 64 : (d - 1))] = vv;
        }
        __syncthreads();

        // S = Q~ K^T (65-dim dot; time pre-negated in q)
        // pairs run along query rows (free from Qt float4 loads)
        u64 s2[4][2] = {};               // [col j][row-pair p]
        #pragma unroll 5
        for (int d = 0; d < DHA; d++) {
            float4 q4 = *(const float4*)&Qt[d * 64 + ty * 4];
            float4 k4 = *(const float4*)&Kt[d * 64 + tx * 4];
            u64 qp0 = pk2(q4.x, q4.y);
            u64 qp1 = pk2(q4.z, q4.w);
            float ka[4] = {k4.x, k4.y, k4.z, k4.w};
            #pragma unroll
            for (int j = 0; j < 4; j++) {
                u64 kbv = bc2(ka[j]);
                fma2(s2[j][0], qp0, kbv);
                fma2(s2[j][1], qp1, kbv);
            }
        }
        {
            u64 sc = bc2(SCALE_F);
            #pragma unroll
            for (int j = 0; j < 4; j++) {
                float2 v01 = up2(mul2(s2[j][0], sc));
                float2 v23 = up2(mul2(s2[j][1], sc));
                *(float4*)&Pt[(tx * 4 + j) * 68 + ty * 4] =
                    make_float4(v01.x, v01.y, v23.x, v23.y);
            }
        }
        __syncthreads();

        // online softmax + time-column PV fold: 4 threads per query row
        {
            int r = tid >> 2;
            int part = tid & 3;
            float mo = mrow[r];
            float mx = -1e30f;
            #pragma unroll
            for (int j = 0; j < 16; j++)
                mx = fmaxf(mx, Pt[(part * 16 + j) * 68 + r]);
            mx = fmaxf(mx, __shfl_xor_sync(0xffffffffu, mx, 1));
            mx = fmaxf(mx, __shfl_xor_sync(0xffffffffu, mx, 2));
            float mn = fmaxf(mo, mx);
            float sum = 0.0f, tsum = 0.0f;
            #pragma unroll
            for (int j = 0; j < 16; j++) {
                int kk = part * 16 + j;
                float v = __expf(Pt[kk * 68 + r] - mn);
                Pt[kk * 68 + r] = v;
                sum += v;
                tsum += v * Vs[kk * 68 + 64];   // broadcast read (N=1)
            }
            sum  += __shfl_xor_sync(0xffffffffu, sum, 1);
            sum  += __shfl_xor_sync(0xffffffffu, sum, 2);
            tsum += __shfl_xor_sync(0xffffffffu, tsum, 1);
            tsum += __shfl_xor_sync(0xffffffffu, tsum, 2);
            if (part == 0) {
                float al = __expf(mo - mn);
                arow[r] = al;
                lrow[r] = lrow[r] * al + sum;
                otacc[r] = otacc[r] * al + tsum;
                mrow[r] = mn;
            }
        }
        __syncthreads();

        // O_space = O*alpha + P @ V  (pairs along V columns, free from float4)
        u64 pacc[4][2] = {};
        #pragma unroll 4
        for (int kk = 0; kk < 64; kk++) {
            float4 p4 = *(const float4*)&Pt[kk * 68 + ty * 4];
            float4 v4 = *(const float4*)&Vs[kk * 68 + tx * 4];
            u64 vp0 = pk2(v4.x, v4.y);
            u64 vp1 = pk2(v4.z, v4.w);
            float pa[4] = {p4.x, p4.y, p4.z, p4.w};
            #pragma unroll
            for (int i = 0; i < 4; i++) {
                u64 pb = bc2(pa[i]);
                fma2(pacc[i][0], pb, vp0);
                fma2(pacc[i][1], pb, vp1);
            }
        }
        #pragma unroll
        for (int i = 0; i < 4; i++) {
            u64 al = bc2(arow[ty * 4 + i]);
            o2[i][0] = fma2v(o2[i][0], al, pacc[i][0]);
            o2[i][1] = fma2v(o2[i][1], al, pacc[i][1]);
        }
    }
    __syncthreads();

    // finalize: s = O/l staged into Pt as [row][dim] (time at col 64)
    #pragma unroll
    for (int i = 0; i < 4; i++) {
        float invl = 1.0f / lrow[ty * 4 + i];
        u64 il = bc2(invl);
        float2 c01 = up2(mul2(o2[i][0], il));
        float2 c23 = up2(mul2(o2[i][1], il));
        *(float4*)&Pt[(ty * 4 + i) * 68 + tx * 4] =
            make_float4(c01.x, c01.y, c23.x, c23.y);
        if (tx == 0) Pt[(ty * 4 + i) * 68 + 64] = otacc[ty * 4 + i] * invl;
    }
    __syncthreads();

    {   // midpoint factor = 1/sqrt(clip(-k*(-t^2 + ||s||^2), eps))
        int r = tid >> 2;
        int part = tid & 3;
        float ss = 0.0f;
        #pragma unroll
        for (int j = 0; j < 16; j++) {
            float v = Pt[r * 68 + part * 16 + j];
            ss += v * v;
        }
        ss += __shfl_xor_sync(0xffffffffu, ss, 1);
        ss += __shfl_xor_sync(0xffffffffu, ss, 2);
        if (part == 0) {
            float t = Pt[r * 68 + 64];
            float inner = ss - t * t;
            arow[r] = rsqrtf(fmaxf(-K_CURV * inner, EPS_F));
        }
    }
    __syncthreads();

    // write normalized space parts into head-concat layout
    for (int lin = tid; lin < 64 * 64; lin += 256) {
        int r = lin >> 6;
        int c = lin & 63;
        int grow = b * NN + n0 + r;
        g_cat[(size_t)grow * DD + 1 + h * DH + c] = Pt[r * 68 + c] * arow[r];
    }
}

// ---------------------------------------------------------------------------
// Kernel 3/5: per-row time attach: col0 = sqrt(clip(INV_K + sumsq(cols 1..512)))
// ---------------------------------------------------------------------------
__global__ void rowtime_kernel(float* outp, int which)
{
    float* buf = which ? g_cat : outp;
    int warp = (blockIdx.x * blockDim.x + threadIdx.x) >> 5;
    int lane = threadIdx.x & 31;
    if (warp >= ROWS) return;
    const float* row = buf + (size_t)warp * DD + 1;
    float s = 0.0f;
    #pragma unroll
    for (int c = lane; c < 512; c += 32) {
        float v = row[c];
        s += v * v;
    }
    #pragma unroll
    for (int off = 16; off; off >>= 1)
        s += __shfl_xor_sync(0xffffffffu, s, off);
    if (lane == 0) buf[(size_t)warp * DD] = sqrtf(fmaxf(INV_K + s, EPS_F));
}

// ---------------------------------------------------------------------------
// Kernel 4: output GEMM: d_out[:,1:513] = g_cat[8192,513] @ Wo[513,512] + bo
// ---------------------------------------------------------------------------
__global__ __launch_bounds__(256) void outproj_kernel(
    const float* __restrict__ Wo, const float* __restrict__ bo,
    float* __restrict__ outp)
{
    __shared__ float As[16][68];
    __shared__ float Bs[16][68];

    const int tid = threadIdx.x;
    const int ty = tid >> 4;
    const int tx = tid & 15;
    const int row0 = blockIdx.x * 64;
    const int col0 = blockIdx.y * 64;

    u64 acc2[4][2] = {};

    for (int k0 = 0; k0 < DD; k0 += 16) {
        #pragma unroll
        for (int i = 0; i < 4; i++) {
            int lin = tid + i * 256;
            int r = lin >> 4;
            int kk = lin & 15;
            int kg = k0 + kk;
            As[kk][r] = (kg < DD) ? g_cat[(size_t)(row0 + r) * DD + kg] : 0.0f;
        }
        #pragma unroll
        for (int i = 0; i < 4; i++) {
            int lin = tid + i * 256;
            int kk = lin >> 6;
            int c = lin & 63;
            int kg = k0 + kk;
            Bs[kk][c] = (kg < DD) ? Wo[(size_t)kg * 512 + col0 + c] : 0.0f;
        }
        __syncthreads();
        #pragma unroll
        for (int kk = 0; kk < 16; kk++) {
            float4 a4 = *(const float4*)&As[kk][ty * 4];
            float4 b4 = *(const float4*)&Bs[kk][tx * 4];
            u64 bp0 = pk2(b4.x, b4.y);
            u64 bp1 = pk2(b4.z, b4.w);
            float av[4] = {a4.x, a4.y, a4.z, a4.w};
            #pragma unroll
            for (int i = 0; i < 4; i++) {
                u64 ab = bc2(av[i]);
                fma2(acc2[i][0], ab, bp0);
                fma2(acc2[i][1], ab, bp1);
            }
        }
        __syncthreads();
    }

    {
        float4 bb = *(const float4*)&bo[col0 + tx * 4];
        #pragma unroll
        for (int i = 0; i < 4; i++) {
            int r = row0 + ty * 4 + i;
            float2 c01 = up2(acc2[i][0]);
            float2 c23 = up2(acc2[i][1]);
            outp[(size_t)r * DD + 1 + col0 + tx * 4 + 0] = c01.x + bb.x;
            outp[(size_t)r * DD + 1 + col0 + tx * 4 + 1] = c01.y + bb.y;
            outp[(size_t)r * DD + 1 + col0 + tx * 4 + 2] = c23.x + bb.z;
            outp[(size_t)r * DD + 1 + col0 + tx * 4 + 3] = c23.y + bb.w;
        }
    }
}

// ---------------------------------------------------------------------------
extern "C" void kernel_launch(void* const* d_in, const int* in_sizes, int n_in,
                              void* d_out, int out_size)
{
    const float* x  = (const float*)d_in[0];
    const float* Wq = (const float*)d_in[1];
    const float* bq = (const float*)d_in[2];
    const float* Wk = (const float*)d_in[3];
    const float* bk = (const float*)d_in[4];
    const float* Wv = (const float*)d_in[5];
    const float* bv = (const float*)d_in[6];
    const float* Wo = (const float*)d_in[7];
    const float* bo = (const float*)d_in[8];
    float* outp = (float*)d_out;

    cudaFuncSetAttribute(attn_kernel,
                         cudaFuncAttributeMaxDynamicSharedMemorySize,
                         ATT_SMEM_BYTES);

    // 1. QKV projections (+time attach, q-time negated)
    proj_kernel<<<dim3(ROWS / 64, 24), 256>>>(x, Wq, bq, Wk, bk, Wv, bv);
    // 2. flash attention + Lorentz midpoint -> g_cat space columns
    attn_kernel<<<dim3(NN / 64, BB * HH), 256, ATT_SMEM_BYTES>>>();
    // 3. concat time component t'
    rowtime_kernel<<<ROWS / 8, 256>>>(nullptr, 1);
    // 4. output projection into d_out[:,1:]
    outproj_kernel<<<dim3(ROWS / 64, 8), 256>>>(Wo, bo, outp);
    // 5. final time attach into d_out[:,0]
    rowtime_kernel<<<ROWS / 8, 256>>>(outp, 0);
}

// round 6
// speedup vs baseline: 1.4087x; 1.3244x over previous
#include <cuda_runtime.h>
#include <math.h>

// Problem dims
#define BB   4
#define NN   2048
#define DD   513
#define HH   8
#define DH   64
#define ROWS (BB*NN)       // 8192

#define INV_K   10.0f
#define K_CURV  0.1f
#define EPS_F   1e-9f
#define SCALE_F 0.125f     // 1/sqrt(64)

// ---------------------------------------------------------------------------
// Packed fp32x2 helpers (sm_100+ PTX fma.rn.f32x2 -> FFMA2)
// ---------------------------------------------------------------------------
typedef unsigned long long u64;
__device__ __forceinline__ u64 pk2(float x, float y) {
    u64 r; asm("mov.b64 %0, {%1,%2};" : "=l"(r) : "f"(x), "f"(y)); return r;
}
__device__ __forceinline__ u64 bc2(float x) {
    u64 r; asm("mov.b64 %0, {%1,%1};" : "=l"(r) : "f"(x)); return r;
}
__device__ __forceinline__ void fma2(u64 &d, u64 a, u64 b) {
    asm("fma.rn.f32x2 %0, %1, %2, %0;" : "+l"(d) : "l"(a), "l"(b));
}
__device__ __forceinline__ u64 fma2v(u64 a, u64 b, u64 c) {
    u64 d; asm("fma.rn.f32x2 %0, %1, %2, %3;" : "=l"(d) : "l"(a), "l"(b), "l"(c)); return d;
}
__device__ __forceinline__ float2 up2(u64 v) {
    float lo, hi; asm("mov.b64 {%0,%1}, %2;" : "=f"(lo), "=f"(hi) : "l"(v));
    return make_float2(lo, hi);
}

// Scratch (device globals: allocation-free per harness rules)
// Space and time split so space arrays are float4-friendly (stride 64).
__device__ float g_qs[BB*HH*NN*DH];   // q space
__device__ float g_qt[BB*HH*NN];      // q time, NEGATED (-> plain 65-dot = Lorentz inner)
__device__ float g_ks[BB*HH*NN*DH];
__device__ float g_kt[BB*HH*NN];
__device__ float g_vs[BB*HH*NN*DH];
__device__ float g_vt[BB*HH*NN];
__device__ float g_cat[ROWS*DD];      // [B*N][513]: col0 = t', cols 1..512 = head-concat space

// ---------------------------------------------------------------------------
// Kernel 1: QKV projection GEMM (128x128 tile, 8x8 micro, FFMA2) + time attach
// grid.y: 0..11 -> mat = y>>2 (q/k/v), col tile = y&3 (covers heads 2c, 2c+1)
// ---------------------------------------------------------------------------
__global__ __launch_bounds__(256) void proj_kernel(
    const float* __restrict__ x,
    const float* __restrict__ Wq, const float* __restrict__ bq,
    const float* __restrict__ Wk, const float* __restrict__ bk,
    const float* __restrict__ Wv, const float* __restrict__ bv)
{
    __shared__ float As[16][132];   // [kk][row]
    __shared__ float Bs[16][132];   // [kk][col]

    const int tid = threadIdx.x;
    const int ty = tid >> 4;        // rows ty*8..+7
    const int tx = tid & 15;        // cols tx*8..+7
    const int row0 = blockIdx.x * 128;
    const int gy = blockIdx.y;
    const int mat = gy >> 2;        // 0=q 1=k 2=v
    const int h0 = (gy & 3) * 2;    // first head in this 128-col tile

    const float* W    = (mat == 0) ? Wq : ((mat == 1) ? Wk : Wv);
    const float* bias = (mat == 0) ? bq : ((mat == 1) ? bk : bv);
    float* outs       = (mat == 0) ? g_qs : ((mat == 1) ? g_ks : g_vs);
    float* outt       = (mat == 0) ? g_qt : ((mat == 1) ? g_kt : g_vt);

    u64 acc2[8][4] = {};            // [row i][col-pair]

    for (int k0 = 0; k0 < DD; k0 += 16) {
        #pragma unroll
        for (int it = 0; it < 8; it++) {          // A: 128 rows x 16 kk, transposed
            int lin = tid + it * 256;
            int r = lin >> 4, kk = lin & 15;
            int kg = k0 + kk;
            As[kk][r] = (kg < DD) ? x[(size_t)(row0 + r) * DD + kg] : 0.0f;
        }
        #pragma unroll
        for (int it = 0; it < 2; it++) {          // B: 16 kk x 128 cols (2 heads)
            int lin = tid + it * 256;
            int kk = lin >> 5, c4 = lin & 31;
            int kg = k0 + kk;
            int c = c4 * 4;
            int h = h0 + (c >> 6), m = c & 63;
            float4 v = make_float4(0.f, 0.f, 0.f, 0.f);
            if (kg < DD) v = *(const float4*)&W[((size_t)h * DD + kg) * DH + m];
            *(float4*)&Bs[kk][c] = v;
        }
        __syncthreads();
        #pragma unroll
        for (int kk = 0; kk < 16; kk++) {
            float4 a0 = *(const float4*)&As[kk][ty * 8];
            float4 a1 = *(const float4*)&As[kk][ty * 8 + 4];
            float4 b0 = *(const float4*)&Bs[kk][tx * 8];
            float4 b1 = *(const float4*)&Bs[kk][tx * 8 + 4];
            u64 bp[4] = {pk2(b0.x, b0.y), pk2(b0.z, b0.w),
                         pk2(b1.x, b1.y), pk2(b1.z, b1.w)};
            float av[8] = {a0.x, a0.y, a0.z, a0.w, a1.x, a1.y, a1.z, a1.w};
            #pragma unroll
            for (int i = 0; i < 8; i++) {
                u64 ab = bc2(av[i]);
                #pragma unroll
                for (int p = 0; p < 4; p++) fma2(acc2[i][p], ab, bp[p]);
            }
        }
        __syncthreads();
    }

    // Epilogue: bias, per-row (per-head) sumsq via shuffle over tx&7, time attach.
    const int hloc = tx >> 3;                  // head within tile
    const int h = h0 + hloc;
    const int m0 = (tx & 7) * 8;               // col within head
    float4 bb0 = *(const float4*)&bias[h * DH + m0];
    float4 bb1 = *(const float4*)&bias[h * DH + m0 + 4];
    const float bbv[8] = {bb0.x, bb0.y, bb0.z, bb0.w, bb1.x, bb1.y, bb1.z, bb1.w};
    const float tsign = (mat == 0) ? -1.0f : 1.0f;

    #pragma unroll
    for (int i = 0; i < 8; i++) {
        float c[8];
        float2 u;
        u = up2(acc2[i][0]); c[0] = u.x + bbv[0]; c[1] = u.y + bbv[1];
        u = up2(acc2[i][1]); c[2] = u.x + bbv[2]; c[3] = u.y + bbv[3];
        u = up2(acc2[i][2]); c[4] = u.x + bbv[4]; c[5] = u.y + bbv[5];
        u = up2(acc2[i][3]); c[6] = u.x + bbv[6]; c[7] = u.y + bbv[7];
        float ss = 0.f;
        #pragma unroll
        for (int j = 0; j < 8; j++) ss += c[j] * c[j];
        ss += __shfl_xor_sync(0xffffffffu, ss, 1);
        ss += __shfl_xor_sync(0xffffffffu, ss, 2);
        ss += __shfl_xor_sync(0xffffffffu, ss, 4);  // full per-head row sumsq
        int g = row0 + ty * 8 + i;
        int b = g >> 11, n = g & 2047;
        size_t bhn = (size_t)(b * HH + h) * NN + n;
        float* dst = &outs[bhn * DH + m0];
        #pragma unroll
        for (int j = 0; j < 8; j++) dst[j] = c[j];
        if ((tx & 7) == 0)
            outt[bhn] = tsign * sqrtf(fmaxf(INV_K + ss, EPS_F));
    }
}

// ---------------------------------------------------------------------------
// Kernel 2: flash attention, 128q x 128k tiles, 256 threads, 8x8 micro (FFMA2)
// Conflict-free smem: Qs/Ks row-major stride 69 (odd -> column reads spread
// banks), Vs stride 68 (float4), Pt [query][key] stride 132, strided row/key
// thread assignment (q = ty+16i, k = tx+16j) so scores store at <=2-way.
// ---------------------------------------------------------------------------
#define AT_QS   0
#define AT_KS   (128*69)
#define AT_VS   (2*128*69)
#define AT_PT   (2*128*69 + 128*68)
#define AT_MR   (AT_PT + 128*132)
#define ATT_SMEM_FLOATS (AT_MR + 4*128)
#define ATT_SMEM_BYTES  (ATT_SMEM_FLOATS * 4)

__global__ __launch_bounds__(256) void attn_kernel()
{
    extern __shared__ float sm[];
    float* Qs   = sm + AT_QS;     // [128][69], time at col 64 (q-time negated)
    float* Ks   = sm + AT_KS;     // [128][69], time at col 64
    float* Vs   = sm + AT_VS;     // [128][68], space 0..63, time at 64
    float* Pt   = sm + AT_PT;     // [128 query][132]
    float* mrow = sm + AT_MR;     // [128]
    float* lrow = mrow + 128;
    float* arow = lrow + 128;
    float* otc  = arow + 128;

    const int tid = threadIdx.x;
    const int ty = tid >> 4;      // queries ty+16i
    const int tx = tid & 15;      // S: keys tx+16j ; PV/epilogue: cols tx*4
    const int bh = blockIdx.y;
    const int q0 = blockIdx.x * 128;
    const int h = bh & 7, b = bh >> 3;

    // stage Q (once)
    const float* qsb = g_qs + ((size_t)bh * NN + q0) * DH;
    const float* qtb = g_qt + (size_t)bh * NN + q0;
    #pragma unroll
    for (int it = 0; it < 8; it++) {
        int lin = tid + it * 256;
        int r = lin >> 4, c4 = lin & 15;
        float4 v = *(const float4*)&qsb[r * DH + c4 * 4];
        float* d = &Qs[r * 69 + c4 * 4];
        d[0] = v.x; d[1] = v.y; d[2] = v.z; d[3] = v.w;
    }
    if (tid < 128) {
        Qs[tid * 69 + 64] = qtb[tid];
        mrow[tid] = -1e30f; lrow[tid] = 0.0f; otc[tid] = 0.0f;
    }

    u64 o2[8][2] = {};            // persistent O: [row i][col-pair]

    const float* ksb = g_ks + (size_t)bh * NN * DH;
    const float* ktb = g_kt + (size_t)bh * NN;
    const float* vsb = g_vs + (size_t)bh * NN * DH;
    const float* vtb = g_vt + (size_t)bh * NN;

    for (int kt = 0; kt < NN / 128; kt++) {
        __syncthreads();
        const float* kp_ = ksb + (size_t)kt * 128 * DH;
        const float* vp_ = vsb + (size_t)kt * 128 * DH;
        #pragma unroll
        for (int it = 0; it < 8; it++) {
            int lin = tid + it * 256;
            int r = lin >> 4, c4 = lin & 15;
            float4 kv = *(const float4*)&kp_[r * DH + c4 * 4];
            float* kd = &Ks[r * 69 + c4 * 4];
            kd[0] = kv.x; kd[1] = kv.y; kd[2] = kv.z; kd[3] = kv.w;
            float4 vv = *(const float4*)&vp_[r * DH + c4 * 4];
            *(float4*)&Vs[r * 68 + c4 * 4] = vv;
        }
        if (tid < 128) {
            Ks[tid * 69 + 64] = ktb[kt * 128 + tid];
            Vs[tid * 68 + 64] = vtb[kt * 128 + tid];
        }
        __syncthreads();

        // ---- S = Q~ K^T over 65 dims (time folded via negated q-time) ----
        {
            u64 s2[8][4] = {};    // [query i][key-pair]
            #pragma unroll 5
            for (int d = 0; d < 65; d++) {
                float qv[8], kv[8];
                #pragma unroll
                for (int i = 0; i < 8; i++) qv[i] = Qs[(ty + 16 * i) * 69 + d];
                #pragma unroll
                for (int j = 0; j < 8; j++) kv[j] = Ks[(tx + 16 * j) * 69 + d];
                u64 kp2[4];
                #pragma unroll
                for (int p = 0; p < 4; p++) kp2[p] = pk2(kv[2 * p], kv[2 * p + 1]);
                #pragma unroll
                for (int i = 0; i < 8; i++) {
                    u64 qb = bc2(qv[i]);
                    #pragma unroll
                    for (int p = 0; p < 4; p++) fma2(s2[i][p], qb, kp2[p]);
                }
            }
            #pragma unroll
            for (int i = 0; i < 8; i++) {
                float* pr = &Pt[(ty + 16 * i) * 132];
                #pragma unroll
                for (int p = 0; p < 4; p++) {
                    float2 v = up2(s2[i][p]);
                    pr[tx + 16 * (2 * p)]     = v.x * SCALE_F;
                    pr[tx + 16 * (2 * p + 1)] = v.y * SCALE_F;
                }
            }
        }
        __syncthreads();

        // ---- online softmax over 128 keys (2 threads/row) + time PV fold ----
        {
            int r = tid >> 1, part = tid & 1;
            float* prow = &Pt[r * 132 + part * 64];
            float mo = mrow[r];
            float mx = -1e30f;
            #pragma unroll
            for (int jf = 0; jf < 16; jf++) {
                float4 p = *(const float4*)&prow[jf * 4];
                mx = fmaxf(mx, fmaxf(fmaxf(p.x, p.y), fmaxf(p.z, p.w)));
            }
            mx = fmaxf(mx, __shfl_xor_sync(0xffffffffu, mx, 1));
            float mn = fmaxf(mo, mx);
            float sum = 0.f, tsum = 0.f;
            #pragma unroll
            for (int jf = 0; jf < 16; jf++) {
                float4 p = *(float4*)&prow[jf * 4];
                float e0 = __expf(p.x - mn), e1 = __expf(p.y - mn);
                float e2 = __expf(p.z - mn), e3 = __expf(p.w - mn);
                *(float4*)&prow[jf * 4] = make_float4(e0, e1, e2, e3);
                sum += (e0 + e1) + (e2 + e3);
                int kk = part * 64 + jf * 4;
                tsum += e0 * Vs[(kk + 0) * 68 + 64] + e1 * Vs[(kk + 1) * 68 + 64]
                      + e2 * Vs[(kk + 2) * 68 + 64] + e3 * Vs[(kk + 3) * 68 + 64];
            }
            sum  += __shfl_xor_sync(0xffffffffu, sum, 1);
            tsum += __shfl_xor_sync(0xffffffffu, tsum, 1);
            if (part == 0) {
                float al = __expf(mo - mn);
                arow[r] = al;
                lrow[r] = lrow[r] * al + sum;
                otc[r]  = otc[r] * al + tsum;
                mrow[r] = mn;
            }
        }
        __syncthreads();

        // ---- O = O*alpha + P @ V (8 rows x 4 cols per thread) ----
        {
            u64 pacc[8][2] = {};
            #pragma unroll 4
            for (int kk = 0; kk < 128; kk++) {
                float4 v4 = *(const float4*)&Vs[kk * 68 + tx * 4];
                u64 vp0 = pk2(v4.x, v4.y), vp1 = pk2(v4.z, v4.w);
                #pragma unroll
                for (int i = 0; i < 8; i++) {
                    u64 pb = bc2(Pt[(ty + 16 * i) * 132 + kk]);
                    fma2(pacc[i][0], pb, vp0);
                    fma2(pacc[i][1], pb, vp1);
                }
            }
            #pragma unroll
            for (int i = 0; i < 8; i++) {
                u64 al = bc2(arow[ty + 16 * i]);
                o2[i][0] = fma2v(o2[i][0], al, pacc[i][0]);
                o2[i][1] = fma2v(o2[i][1], al, pacc[i][1]);
            }
        }
    }

    // ---- epilogue: normalize, Lorentz midpoint factor, write head-concat ----
    #pragma unroll
    for (int i = 0; i < 8; i++) {
        int q = ty + 16 * i;
        float invl = 1.0f / lrow[q];
        float2 c01 = up2(o2[i][0]);
        float2 c23 = up2(o2[i][1]);
        float c0 = c01.x * invl, c1 = c01.y * invl;
        float c2 = c23.x * invl, c3 = c23.y * invl;
        float t = otc[q] * invl;
        float ss = c0 * c0 + c1 * c1 + c2 * c2 + c3 * c3;
        ss += __shfl_xor_sync(0xffffffffu, ss, 1);
        ss += __shfl_xor_sync(0xffffffffu, ss, 2);
        ss += __shfl_xor_sync(0xffffffffu, ss, 4);
        ss += __shfl_xor_sync(0xffffffffu, ss, 8);   // full 64-col row sumsq
        float fac = rsqrtf(fmaxf(-K_CURV * (ss - t * t), EPS_F));
        float* dst = &g_cat[(size_t)(b * NN + q0 + q) * DD + 1 + h * DH + tx * 4];
        dst[0] = c0 * fac; dst[1] = c1 * fac; dst[2] = c2 * fac; dst[3] = c3 * fac;
    }
}

// ---------------------------------------------------------------------------
// Kernel 3/5: per-row time attach: col0 = sqrt(clip(INV_K + sumsq(cols 1..512)))
// ---------------------------------------------------------------------------
__global__ void rowtime_kernel(float* outp, int which)
{
    float* buf = which ? g_cat : outp;
    int warp = (blockIdx.x * blockDim.x + threadIdx.x) >> 5;
    int lane = threadIdx.x & 31;
    if (warp >= ROWS) return;
    const float* row = buf + (size_t)warp * DD + 1;
    float s = 0.0f;
    #pragma unroll
    for (int c = lane; c < 512; c += 32) {
        float v = row[c];
        s += v * v;
    }
    #pragma unroll
    for (int off = 16; off; off >>= 1)
        s += __shfl_xor_sync(0xffffffffu, s, off);
    if (lane == 0) buf[(size_t)warp * DD] = sqrtf(fmaxf(INV_K + s, EPS_F));
}

// ---------------------------------------------------------------------------
// Kernel 4: output GEMM: d_out[:,1:513] = g_cat[8192,513] @ Wo[513,512] + bo
// 128x128 tile, 8x8 micro, FFMA2.
// ---------------------------------------------------------------------------
__global__ __launch_bounds__(256) void outproj_kernel(
    const float* __restrict__ Wo, const float* __restrict__ bo,
    float* __restrict__ outp)
{
    __shared__ float As[16][132];
    __shared__ float Bs[16][132];

    const int tid = threadIdx.x;
    const int ty = tid >> 4;
    const int tx = tid & 15;
    const int row0 = blockIdx.x * 128;
    const int col0 = blockIdx.y * 128;

    u64 acc2[8][4] = {};

    for (int k0 = 0; k0 < DD; k0 += 16) {
        #pragma unroll
        for (int it = 0; it < 8; it++) {
            int lin = tid + it * 256;
            int r = lin >> 4, kk = lin & 15;
            int kg = k0 + kk;
            As[kk][r] = (kg < DD) ? g_cat[(size_t)(row0 + r) * DD + kg] : 0.0f;
        }
        #pragma unroll
        for (int it = 0; it < 2; it++) {
            int lin = tid + it * 256;
            int kk = lin >> 5, c4 = lin & 31;
            int kg = k0 + kk;
            float4 v = make_float4(0.f, 0.f, 0.f, 0.f);
            if (kg < DD) v = *(const float4*)&Wo[(size_t)kg * 512 + col0 + c4 * 4];
            *(float4*)&Bs[kk][c4 * 4] = v;
        }
        __syncthreads();
        #pragma unroll
        for (int kk = 0; kk < 16; kk++) {
            float4 a0 = *(const float4*)&As[kk][ty * 8];
            float4 a1 = *(const float4*)&As[kk][ty * 8 + 4];
            float4 b0 = *(const float4*)&Bs[kk][tx * 8];
            float4 b1 = *(const float4*)&Bs[kk][tx * 8 + 4];
            u64 bp[4] = {pk2(b0.x, b0.y), pk2(b0.z, b0.w),
                         pk2(b1.x, b1.y), pk2(b1.z, b1.w)};
            float av[8] = {a0.x, a0.y, a0.z, a0.w, a1.x, a1.y, a1.z, a1.w};
            #pragma unroll
            for (int i = 0; i < 8; i++) {
                u64 ab = bc2(av[i]);
                #pragma unroll
                for (int p = 0; p < 4; p++) fma2(acc2[i][p], ab, bp[p]);
            }
        }
        __syncthreads();
    }

    float4 bb0 = *(const float4*)&bo[col0 + tx * 8];
    float4 bb1 = *(const float4*)&bo[col0 + tx * 8 + 4];
    const float bbv[8] = {bb0.x, bb0.y, bb0.z, bb0.w, bb1.x, bb1.y, bb1.z, bb1.w};
    #pragma unroll
    for (int i = 0; i < 8; i++) {
        float c[8];
        float2 u;
        u = up2(acc2[i][0]); c[0] = u.x; c[1] = u.y;
        u = up2(acc2[i][1]); c[2] = u.x; c[3] = u.y;
        u = up2(acc2[i][2]); c[4] = u.x; c[5] = u.y;
        u = up2(acc2[i][3]); c[6] = u.x; c[7] = u.y;
        float* dst = &outp[(size_t)(row0 + ty * 8 + i) * DD + 1 + col0 + tx * 8];
        #pragma unroll
        for (int j = 0; j < 8; j++) dst[j] = c[j] + bbv[j];
    }
}

// ---------------------------------------------------------------------------
extern "C" void kernel_launch(void* const* d_in, const int* in_sizes, int n_in,
                              void* d_out, int out_size)
{
    const float* x  = (const float*)d_in[0];
    const float* Wq = (const float*)d_in[1];
    const float* bq = (const float*)d_in[2];
    const float* Wk = (const float*)d_in[3];
    const float* bk = (const float*)d_in[4];
    const float* Wv = (const float*)d_in[5];
    const float* bv = (const float*)d_in[6];
    const float* Wo = (const float*)d_in[7];
    const float* bo = (const float*)d_in[8];
    float* outp = (float*)d_out;

    cudaFuncSetAttribute(attn_kernel,
                         cudaFuncAttributeMaxDynamicSharedMemorySize,
                         ATT_SMEM_BYTES);

    // 1. QKV projections (+time attach, q-time negated)
    proj_kernel<<<dim3(ROWS / 128, 12), 256>>>(x, Wq, bq, Wk, bk, Wv, bv);
    // 2. flash attention + Lorentz midpoint -> g_cat space columns
    attn_kernel<<<dim3(NN / 128, BB * HH), 256, ATT_SMEM_BYTES>>>();
    // 3. concat time component t'
    rowtime_kernel<<<ROWS / 8, 256>>>(nullptr, 1);
    // 4. output projection into d_out[:,1:]
    outproj_kernel<<<dim3(ROWS / 128, 4), 256>>>(Wo, bo, outp);
    // 5. final time attach into d_out[:,0]
    rowtime_kernel<<<ROWS / 8, 256>>>(outp, 0);
}